// round 3
// baseline (speedup 1.0000x reference)
#include <cuda_runtime.h>
#include <math.h>

// ---------------- static device scratch (no allocation allowed) ----------------
#define MAXE_256 (2*256*96*160)   // 7,864,320 floats
#define MAXE_128 (2*128*96*160)   // 3,932,160 floats
__device__ float g_bufA[MAXE_256];
__device__ float g_bufB[MAXE_256];
__device__ float g_mA[MAXE_128];
__device__ float g_mB[MAXE_128];
__device__ float g_mC[MAXE_128];
__device__ float g_stats[128];
__device__ float g_params[200*169];
__device__ float g_dyn[200*96*160];

// ---------------- conv3x3, SAME pad, direct, register-blocked ----------------
// Block tile: 64 out-channels x (8 rows x 32 cols) pixels.
// 256 threads: col = tid&31, ocg = tid>>5 ; each thread: 8 rows x 8 ocs.
__global__ void __launch_bounds__(256, 2)
conv3x3_kernel(const float* __restrict__ in, const float* __restrict__ wgt,
               const float* __restrict__ bias, const float* __restrict__ scale_ptr,
               float* __restrict__ out,
               int N, int CIN, int CO, int H, int W)
{
    __shared__ float s_in[8][10][34];   // 8 ic x (8+2) x (32+2)
    __shared__ float s_w[8][9][64];     // 8 ic x 9 taps x 64 oc

    int tiles_y = (H + 7) >> 3;
    int tx0 = blockIdx.x * 32;
    int ty0 = (blockIdx.y % tiles_y) * 8;
    int n   = blockIdx.y / tiles_y;
    int oc0 = blockIdx.z * 64;
    int tid = threadIdx.x;
    int col = tid & 31;
    int ocg = tid >> 5;

    float acc[8][8];
    #pragma unroll
    for (int r = 0; r < 8; r++)
        #pragma unroll
        for (int o = 0; o < 8; o++) acc[r][o] = 0.f;

    const float* in_n = in + (size_t)n * CIN * H * W;

    for (int ic0 = 0; ic0 < CIN; ic0 += 8) {
        __syncthreads();
        // load input tile (zero-padded halo)
        for (int i = tid; i < 8*10*34; i += 256) {
            int c  = i / 340;
            int rem = i % 340;
            int r  = rem / 34;
            int cc = rem % 34;
            int gy = ty0 + r - 1, gx = tx0 + cc - 1;
            float v = 0.f;
            if (gy >= 0 && gy < H && gx >= 0 && gx < W)
                v = in_n[(size_t)(ic0 + c) * H * W + (size_t)gy * W + gx];
            s_in[c][r][cc] = v;
        }
        // load weights: wgt layout [CO][CIN][3][3]
        for (int i = tid; i < 8*9*64; i += 256) {
            int c   = i / (9*64);
            int rem = i % (9*64);
            int t   = rem / 64;
            int oc  = rem % 64;
            float v = 0.f;
            if (oc0 + oc < CO)
                v = wgt[((size_t)(oc0 + oc) * CIN + (ic0 + c)) * 9 + t];
            s_w[c][t][oc] = v;
        }
        __syncthreads();

        #pragma unroll 1
        for (int c = 0; c < 8; c++) {
            #pragma unroll
            for (int ky = 0; ky < 3; ky++) {
                #pragma unroll
                for (int kx = 0; kx < 3; kx++) {
                    float4 w0 = *(const float4*)&s_w[c][ky*3+kx][ocg*8];
                    float4 w1 = *(const float4*)&s_w[c][ky*3+kx][ocg*8+4];
                    #pragma unroll
                    for (int r = 0; r < 8; r++) {
                        float iv = s_in[c][r+ky][col+kx];
                        acc[r][0] += iv * w0.x; acc[r][1] += iv * w0.y;
                        acc[r][2] += iv * w0.z; acc[r][3] += iv * w0.w;
                        acc[r][4] += iv * w1.x; acc[r][5] += iv * w1.y;
                        acc[r][6] += iv * w1.z; acc[r][7] += iv * w1.w;
                    }
                }
            }
        }
    }

    float sc = scale_ptr ? *scale_ptr : 1.0f;
    int gx = tx0 + col;
    if (gx < W) {
        #pragma unroll
        for (int r = 0; r < 8; r++) {
            int gy = ty0 + r;
            if (gy >= H) break;
            #pragma unroll
            for (int o = 0; o < 8; o++) {
                int oc = oc0 + ocg*8 + o;
                if (oc < CO) {
                    float v = acc[r][o] * sc + (bias ? bias[oc] : 0.f);
                    out[((size_t)(n * CO + oc) * H + gy) * W + gx] = v;
                }
            }
        }
    }
}

// ---------------- GroupNorm: zero / stats / apply ----------------
__global__ void zero_kernel(float* p, int n)
{
    int i = blockIdx.x * blockDim.x + threadIdx.x;
    if (i < n) p[i] = 0.f;
}

// One (group, slab) per block. Groups are contiguous slabs of E elements.
__global__ void gn_stats_kernel(const float* __restrict__ x, float* __restrict__ stats, int E)
{
    int gi = blockIdx.y;
    const float* p = x + (size_t)gi * E;
    float s1 = 0.f, s2 = 0.f;
    for (int i = blockIdx.x * blockDim.x + threadIdx.x; i < E; i += gridDim.x * blockDim.x) {
        float v = p[i];
        s1 += v; s2 += v * v;
    }
    // warp reduce
    #pragma unroll
    for (int o = 16; o; o >>= 1) {
        s1 += __shfl_down_sync(0xffffffffu, s1, o);
        s2 += __shfl_down_sync(0xffffffffu, s2, o);
    }
    __shared__ float r1[32], r2[32];
    int w = threadIdx.x >> 5, l = threadIdx.x & 31;
    if (l == 0) { r1[w] = s1; r2[w] = s2; }
    __syncthreads();
    if (w == 0) {
        int nw = blockDim.x >> 5;
        s1 = (l < nw) ? r1[l] : 0.f;
        s2 = (l < nw) ? r2[l] : 0.f;
        #pragma unroll
        for (int o = 16; o; o >>= 1) {
            s1 += __shfl_down_sync(0xffffffffu, s1, o);
            s2 += __shfl_down_sync(0xffffffffu, s2, o);
        }
        if (l == 0) {
            atomicAdd(&stats[gi*2],   s1);
            atomicAdd(&stats[gi*2+1], s2);
        }
    }
}

__global__ void gn_apply_kernel(const float* __restrict__ x, const float* __restrict__ stats,
                                const float* __restrict__ gg, const float* __restrict__ bb,
                                float* __restrict__ out,
                                int total, int CHW, int HW, int Cg, int groups, int relu)
{
    int i = blockIdx.x * blockDim.x + threadIdx.x;
    if (i >= total) return;
    int n = i / CHW;
    int c = (i % CHW) / HW;
    int gi = n * groups + c / Cg;
    float E  = (float)Cg * (float)HW;
    float s1 = stats[gi*2], s2 = stats[gi*2+1];
    float mu  = s1 / E;
    float var = s2 / E - mu * mu;
    float rs  = rsqrtf(var + 1e-5f);
    float v = (x[i] - mu) * rs * gg[c] + bb[c];
    if (relu) v = fmaxf(v, 0.f);
    out[i] = v;
}

// ---------------- 1x1 conv 128 -> 8 ----------------
__global__ void conv1x1_8_kernel(const float* __restrict__ in, const float* __restrict__ w,
                                 float* __restrict__ out, int N, int CIN, int HW)
{
    __shared__ float sw[8*128];
    for (int i = threadIdx.x; i < 8*CIN; i += blockDim.x) sw[i] = w[i];
    __syncthreads();
    int p = blockIdx.x * blockDim.x + threadIdx.x;
    if (p >= N * HW) return;
    int n = p / HW, pp = p % HW;
    const float* ip = in + (size_t)n * CIN * HW + pp;
    float a[8] = {0,0,0,0,0,0,0,0};
    for (int c = 0; c < CIN; c++) {
        float v = ip[(size_t)c * HW];
        #pragma unroll
        for (int o = 0; o < 8; o++) a[o] += sw[o*CIN + c] * v;
    }
    #pragma unroll
    for (int o = 0; o < 8; o++)
        out[((size_t)(n*8 + o)) * HW + pp] = a[o];
}

// ---------------- bilinear resize (align-corners linspace), optional add ----------------
__global__ void resize_kernel(const float* __restrict__ src, float* __restrict__ dst,
                              int NC, int sH, int sW, int dH, int dW, int add)
{
    int i = blockIdx.x * blockDim.x + threadIdx.x;
    int tot = NC * dH * dW;
    if (i >= tot) return;
    int x = i % dW;
    int y = (i / dW) % dH;
    int c = i / (dW * dH);
    float fy = (dH > 1) ? (float)y * (float)(sH - 1) / (float)(dH - 1) : 0.f;
    float fx = (dW > 1) ? (float)x * (float)(sW - 1) / (float)(dW - 1) : 0.f;
    int y0 = (int)floorf(fy); int y1 = min(y0 + 1, sH - 1); float wy = fy - (float)y0;
    int x0 = (int)floorf(fx); int x1 = min(x0 + 1, sW - 1); float wx = fx - (float)x0;
    const float* sp = src + (size_t)c * sH * sW;
    float v00 = sp[(size_t)y0*sW + x0], v01 = sp[(size_t)y0*sW + x1];
    float v10 = sp[(size_t)y1*sW + x0], v11 = sp[(size_t)y1*sW + x1];
    float t0 = v00 * (1.f - wy) + v10 * wy;
    float t1 = v01 * (1.f - wy) + v11 * wy;
    float v  = t0 * (1.f - wx) + t1 * wx;
    if (add) dst[i] += v; else dst[i] = v;
}

// ---------------- gather controller params from pred3 ----------------
// params[(b*100+j), p] = pred3[b, 85+p, 0, j]  (first 100 flattened spatial positions)
__global__ void gather_params_kernel(const float* __restrict__ pred3, float* __restrict__ params)
{
    int i = blockIdx.x * blockDim.x + threadIdx.x;
    if (i >= 200*169) return;
    int inst = i / 169, p = i % 169;
    int b = inst / 100, j = inst % 100;
    params[i] = pred3[((size_t)(b*254 + 85 + p)) * (96*160) + j];
}

// ---------------- fused 3-layer dynamic conv MLP ----------------
__global__ void dyn_mlp_kernel(const float* __restrict__ mf, const float* __restrict__ params,
                               float* __restrict__ out)
{
    __shared__ float P[169];
    int inst = blockIdx.x;
    for (int i = threadIdx.x; i < 169; i += blockDim.x) P[i] = params[inst*169 + i];
    __syncthreads();
    int b = inst / 100;
    const int HW = 96*160;
    for (int p = blockIdx.y * blockDim.x + threadIdx.x; p < HW; p += gridDim.y * blockDim.x) {
        int row = p / 160, colx = p % 160;
        float in[10];
        #pragma unroll
        for (int c = 0; c < 8; c++) in[c] = mf[((size_t)(b*8 + c)) * HW + p];
        in[8] = -1.f + 2.f * (float)colx / 159.f;   // xx (cols)
        in[9] = -1.f + 2.f * (float)row  / 95.f;    // yy (rows)
        float h1[8];
        #pragma unroll
        for (int o = 0; o < 8; o++) {
            float s = P[152 + o];
            #pragma unroll
            for (int c = 0; c < 10; c++) s += P[o*10 + c] * in[c];
            h1[o] = fmaxf(s, 0.f);
        }
        float h2[8];
        #pragma unroll
        for (int o = 0; o < 8; o++) {
            float s = P[160 + o];
            #pragma unroll
            for (int c = 0; c < 8; c++) s += P[80 + o*8 + c] * h1[c];
            h2[o] = fmaxf(s, 0.f);
        }
        float s3 = P[168];
        #pragma unroll
        for (int c = 0; c < 8; c++) s3 += P[144 + c] * h2[c];
        out[(size_t)inst * HW + p] = s3;
    }
}

// ---------------- host orchestration ----------------
static void run_conv(const float* in, const float* w, const float* bias, const float* scale,
                     float* out, int N, int CIN, int CO, int H, int W)
{
    dim3 grid((W + 31) / 32, ((H + 7) / 8) * N, (CO + 63) / 64);
    conv3x3_kernel<<<grid, 256>>>(in, w, bias, scale, out, N, CIN, CO, H, W);
}

static void run_gn(const float* x, float* out, const float* g, const float* b,
                   float* stats, int N, int C, int H, int W, int groups, int relu)
{
    int Cg = C / groups;
    int E = Cg * H * W;
    int ng = N * groups;
    zero_kernel<<<1, 128>>>(stats, ng * 2);
    int slabs = E / 8192; if (slabs < 1) slabs = 1; if (slabs > 64) slabs = 64;
    dim3 gs(slabs, ng);
    gn_stats_kernel<<<gs, 256>>>(x, stats, E);
    int total = N * C * H * W;
    gn_apply_kernel<<<(total + 255) / 256, 256>>>(x, stats, g, b, out,
                                                  total, C * H * W, H * W, Cg, groups, relu);
}

extern "C" void kernel_launch(void* const* d_in, const int* in_sizes, int n_in,
                              void* d_out, int out_size)
{
    const int HS[5] = {96, 48, 24, 12, 6};
    const int WS[5] = {160, 80, 40, 20, 10};

    const float* f[5];
    for (int i = 0; i < 5; i++) f[i] = (const float*)d_in[i];
    const float* head_w     = (const float*)d_in[5];
    const float* head_gn_g  = (const float*)d_in[6];
    const float* head_gn_b  = (const float*)d_in[7];
    const float* head_out_w = (const float*)d_in[8];
    const float* head_out_b = (const float*)d_in[9];
    const float* scales     = (const float*)d_in[10];
    const float* ref_w      = (const float*)d_in[11];
    const float* ref_gn_g   = (const float*)d_in[12];
    const float* ref_gn_b   = (const float*)d_in[13];
    const float* tow_w      = (const float*)d_in[14];
    const float* tow_gn_g   = (const float*)d_in[15];
    const float* tow_gn_b   = (const float*)d_in[16];
    const float* out_w      = (const float*)d_in[17];
    const float* out_gn_g   = (const float*)d_in[18];
    const float* out_gn_b   = (const float*)d_in[19];

    float *bufA, *bufB, *mA, *mB, *mC, *stats, *params, *dyn;
    cudaGetSymbolAddress((void**)&bufA,   g_bufA);
    cudaGetSymbolAddress((void**)&bufB,   g_bufB);
    cudaGetSymbolAddress((void**)&mA,     g_mA);
    cudaGetSymbolAddress((void**)&mB,     g_mB);
    cudaGetSymbolAddress((void**)&mC,     g_mC);
    cudaGetSymbolAddress((void**)&stats,  g_stats);
    cudaGetSymbolAddress((void**)&params, g_params);
    cudaGetSymbolAddress((void**)&dyn,    g_dyn);

    float* out = (float*)d_out;

    // output offsets (pred3..pred7, mask_feats, mask_logits)
    size_t pred_off[5];
    size_t off = 0;
    for (int L = 0; L < 5; L++) {
        pred_off[L] = off;
        off += (size_t)2 * 254 * HS[L] * WS[L];
    }
    size_t mf_off = off;            // 2*8*96*160
    off += (size_t)2 * 8 * 96 * 160;
    size_t ml_off = off;            // 200*192*320

    // ---- head branches (shared weights, 5 levels) ----
    for (int L = 0; L < 5; L++) {
        int H = HS[L], W = WS[L];
        const float* x = f[L];
        for (int i = 0; i < 4; i++) {
            run_conv(x, head_w + (size_t)i * 256 * 256 * 9, nullptr, nullptr,
                     bufA, 2, 256, 256, H, W);
            run_gn(bufA, bufB, head_gn_g + i * 256, head_gn_b + i * 256,
                   stats, 2, 256, H, W, 32, 1);
            x = bufB;
        }
        run_conv(x, head_out_w, head_out_b, scales + L,
                 out + pred_off[L], 2, 256, 254, H, W);
    }

    // ---- mask branch: refine levels 0..2, accumulate at level-0 resolution ----
    for (int i = 0; i < 3; i++) {
        int H = HS[i], W = WS[i];
        run_conv(f[i], ref_w + (size_t)i * 128 * 256 * 9, nullptr, nullptr,
                 mA, 2, 256, 128, H, W);
        if (i == 0) {
            run_gn(mA, mC, ref_gn_g + i * 128, ref_gn_b + i * 128, stats, 2, 128, H, W, 1, 1);
        } else {
            run_gn(mA, mB, ref_gn_g + i * 128, ref_gn_b + i * 128, stats, 2, 128, H, W, 1, 1);
            int tot = 2 * 128 * 96 * 160;
            resize_kernel<<<(tot + 255) / 256, 256>>>(mB, mC, 2 * 128, H, W, 96, 160, 1);
        }
    }
    // ---- tower (4 convs, ping-pong mB/mC with mA as raw) ----
    const float* tx = mC;
    for (int i = 0; i < 4; i++) {
        run_conv(tx, tow_w + (size_t)i * 128 * 128 * 9, nullptr, nullptr,
                 mA, 2, 128, 128, 96, 160);
        float* dst = (i % 2 == 0) ? mB : mC;
        run_gn(mA, dst, tow_gn_g + i * 128, tow_gn_b + i * 128, stats, 2, 128, 96, 160, 1, 1);
        tx = dst;
    }
    // ---- out 1x1 conv -> GN -> relu -> mask_feats (into d_out) ----
    {
        int HW = 96 * 160;
        conv1x1_8_kernel<<<(2 * HW + 255) / 256, 256>>>(tx, out_w, mA, 2, 128, HW);
        run_gn(mA, out + mf_off, out_gn_g, out_gn_b, stats, 2, 8, 96, 160, 1, 1);
    }
    // ---- dynamic conv head ----
    gather_params_kernel<<<(200 * 169 + 255) / 256, 256>>>(out + pred_off[0], params);
    {
        dim3 g(200, 60);
        dyn_mlp_kernel<<<g, 256>>>(out + mf_off, params, dyn);
    }
    {
        int tot = 200 * 192 * 320;
        resize_kernel<<<(tot + 255) / 256, 256>>>(dyn, out + ml_off, 200, 96, 160, 192, 320, 0);
    }
}

// round 4
// speedup vs baseline: 1.0346x; 1.0346x over previous
#include <cuda_runtime.h>
#include <math.h>

// ---------------- static device scratch (no allocation allowed) ----------------
#define MAXE_256 (2*256*96*160)   // 7,864,320 floats
#define MAXE_128 (2*128*96*160)   // 3,932,160 floats
__device__ float g_bufA[MAXE_256];
__device__ float g_bufB[MAXE_256];
__device__ float g_mA[MAXE_128];
__device__ float g_mB[MAXE_128];
__device__ float g_mC[MAXE_128];
__device__ float g_stats[32*128];
__device__ float g_params[200*169];
__device__ float g_dyn[200*96*160];

// packed fp32x2 FMA: d = a*b + d (lanewise on 64-bit register pairs)
#define FFMA2(d, a, b) \
    asm("fma.rn.f32x2 %0, %1, %2, %0;" : "+l"(d) : "l"(a), "l"(b))

// ---------------- conv3x3, SAME pad, direct, register-blocked, f32x2 ----------------
// Block tile: 64 out-channels x (8 rows x 32 cols) pixels.
// 256 threads: col = tid&31, ocg = tid>>5 ; each thread: 8 rows x 8 ocs (4 oc-pairs).
__global__ void __launch_bounds__(256, 2)
conv3x3_kernel(const float* __restrict__ in, const float* __restrict__ wgt,
               const float* __restrict__ bias, const float* __restrict__ scale_ptr,
               float* __restrict__ out,
               int N, int CIN, int CO, int H, int W)
{
    __shared__ __align__(16) float2 s_in[8][10][34];  // duplicated {v,v}: 21,760 B
    __shared__ __align__(16) float  s_w[8][9][64];    // 18,432 B

    int tiles_y = (H + 7) >> 3;
    int tx0 = blockIdx.x * 32;
    int ty0 = (blockIdx.y % tiles_y) * 8;
    int n   = blockIdx.y / tiles_y;
    int oc0 = blockIdx.z * 64;
    int tid = threadIdx.x;
    int col = tid & 31;
    int ocg = tid >> 5;

    unsigned long long acc[8][4];
    #pragma unroll
    for (int r = 0; r < 8; r++)
        #pragma unroll
        for (int p = 0; p < 4; p++) acc[r][p] = 0ull;

    const float* in_n = in + (size_t)n * CIN * H * W;

    for (int ic0 = 0; ic0 < CIN; ic0 += 8) {
        __syncthreads();
        // load input tile (zero-padded halo), duplicated into float2{v,v}
        for (int i = tid; i < 8*10*34; i += 256) {
            int c   = i / 340;
            int rem = i % 340;
            int r   = rem / 34;
            int cc  = rem % 34;
            int gy = ty0 + r - 1, gx = tx0 + cc - 1;
            float v = 0.f;
            if (gy >= 0 && gy < H && gx >= 0 && gx < W)
                v = in_n[(size_t)(ic0 + c) * H * W + (size_t)gy * W + gx];
            s_in[c][r][cc] = make_float2(v, v);
        }
        // load weights: wgt layout [CO][CIN][3][3] -> s_w[ic][tap][oc]
        for (int i = tid; i < 8*9*64; i += 256) {
            int c   = i / (9*64);
            int rem = i % (9*64);
            int t   = rem / 64;
            int oc  = rem % 64;
            float v = 0.f;
            if (oc0 + oc < CO)
                v = wgt[((size_t)(oc0 + oc) * CIN + (ic0 + c)) * 9 + t];
            s_w[c][t][oc] = v;
        }
        __syncthreads();

        #pragma unroll 1
        for (int c = 0; c < 8; c++) {
            #pragma unroll
            for (int ky = 0; ky < 3; ky++) {
                #pragma unroll
                for (int kx = 0; kx < 3; kx++) {
                    // 8 weights (4 f32x2 pairs) broadcast per warp
                    ulonglong2 w0 = *(const ulonglong2*)&s_w[c][ky*3+kx][ocg*8];
                    ulonglong2 w1 = *(const ulonglong2*)&s_w[c][ky*3+kx][ocg*8+4];
                    #pragma unroll
                    for (int r = 0; r < 8; r++) {
                        unsigned long long iv =
                            *(const unsigned long long*)&s_in[c][r+ky][col+kx];
                        FFMA2(acc[r][0], iv, w0.x);
                        FFMA2(acc[r][1], iv, w0.y);
                        FFMA2(acc[r][2], iv, w1.x);
                        FFMA2(acc[r][3], iv, w1.y);
                    }
                }
            }
        }
    }

    float sc = scale_ptr ? *scale_ptr : 1.0f;
    int gx = tx0 + col;
    if (gx < W) {
        #pragma unroll
        for (int r = 0; r < 8; r++) {
            int gy = ty0 + r;
            if (gy >= H) break;
            #pragma unroll
            for (int p = 0; p < 4; p++) {
                unsigned lo = (unsigned)(acc[r][p] & 0xffffffffull);
                unsigned hi = (unsigned)(acc[r][p] >> 32);
                int oc_lo = oc0 + ocg*8 + 2*p;
                if (oc_lo < CO) {
                    float v = __uint_as_float(lo) * sc + (bias ? bias[oc_lo] : 0.f);
                    out[((size_t)(n * CO + oc_lo) * H + gy) * W + gx] = v;
                }
                if (oc_lo + 1 < CO) {
                    float v = __uint_as_float(hi) * sc + (bias ? bias[oc_lo+1] : 0.f);
                    out[((size_t)(n * CO + oc_lo + 1) * H + gy) * W + gx] = v;
                }
            }
        }
    }
}

// ---------------- GroupNorm: zero / stats / apply ----------------
__global__ void zero_kernel(float* p, int n)
{
    int i = blockIdx.x * blockDim.x + threadIdx.x;
    if (i < n) p[i] = 0.f;
}

// One (group, slab) per block. Groups are contiguous slabs of E elements (E % 4 == 0).
__global__ void gn_stats_kernel(const float* __restrict__ x, float* __restrict__ stats, int E)
{
    int gi = blockIdx.y;
    const float4* p = (const float4*)(x + (size_t)gi * E);
    int E4 = E >> 2;
    float s1 = 0.f, s2 = 0.f;
    for (int i = blockIdx.x * blockDim.x + threadIdx.x; i < E4; i += gridDim.x * blockDim.x) {
        float4 v = p[i];
        s1 += v.x + v.y + v.z + v.w;
        s2 += v.x*v.x + v.y*v.y + v.z*v.z + v.w*v.w;
    }
    #pragma unroll
    for (int o = 16; o; o >>= 1) {
        s1 += __shfl_down_sync(0xffffffffu, s1, o);
        s2 += __shfl_down_sync(0xffffffffu, s2, o);
    }
    __shared__ float r1[32], r2[32];
    int w = threadIdx.x >> 5, l = threadIdx.x & 31;
    if (l == 0) { r1[w] = s1; r2[w] = s2; }
    __syncthreads();
    if (w == 0) {
        int nw = blockDim.x >> 5;
        s1 = (l < nw) ? r1[l] : 0.f;
        s2 = (l < nw) ? r2[l] : 0.f;
        #pragma unroll
        for (int o = 16; o; o >>= 1) {
            s1 += __shfl_down_sync(0xffffffffu, s1, o);
            s2 += __shfl_down_sync(0xffffffffu, s2, o);
        }
        if (l == 0) {
            atomicAdd(&stats[gi*2],   s1);
            atomicAdd(&stats[gi*2+1], s2);
        }
    }
}

// vectorized over float4 (HW % 4 == 0 so a vector never crosses a channel)
__global__ void gn_apply_kernel(const float* __restrict__ x, const float* __restrict__ stats,
                                const float* __restrict__ gg, const float* __restrict__ bb,
                                float* __restrict__ out,
                                int total4, int CHW4, int HW4, int Cg, int groups, int relu,
                                float invE)
{
    int i = blockIdx.x * blockDim.x + threadIdx.x;
    if (i >= total4) return;
    int n = i / CHW4;
    int c = (i % CHW4) / HW4;
    int gi = n * groups + c / Cg;
    float s1 = stats[gi*2], s2 = stats[gi*2+1];
    float mu  = s1 * invE;
    float var = s2 * invE - mu * mu;
    float rs  = rsqrtf(var + 1e-5f);
    float a = rs * gg[c];
    float b = bb[c] - mu * a;
    float4 v = ((const float4*)x)[i];
    v.x = v.x * a + b; v.y = v.y * a + b; v.z = v.z * a + b; v.w = v.w * a + b;
    if (relu) {
        v.x = fmaxf(v.x, 0.f); v.y = fmaxf(v.y, 0.f);
        v.z = fmaxf(v.z, 0.f); v.w = fmaxf(v.w, 0.f);
    }
    ((float4*)out)[i] = v;
}

// ---------------- 1x1 conv 128 -> 8 ----------------
__global__ void conv1x1_8_kernel(const float* __restrict__ in, const float* __restrict__ w,
                                 float* __restrict__ out, int N, int CIN, int HW)
{
    __shared__ float sw[8*128];
    for (int i = threadIdx.x; i < 8*CIN; i += blockDim.x) sw[i] = w[i];
    __syncthreads();
    int p = blockIdx.x * blockDim.x + threadIdx.x;
    if (p >= N * HW) return;
    int n = p / HW, pp = p % HW;
    const float* ip = in + (size_t)n * CIN * HW + pp;
    float a[8] = {0,0,0,0,0,0,0,0};
    for (int c = 0; c < CIN; c++) {
        float v = ip[(size_t)c * HW];
        #pragma unroll
        for (int o = 0; o < 8; o++) a[o] += sw[o*CIN + c] * v;
    }
    #pragma unroll
    for (int o = 0; o < 8; o++)
        out[((size_t)(n*8 + o)) * HW + pp] = a[o];
}

// ---------------- bilinear resize (align-corners linspace), optional add ----------------
__global__ void resize_kernel(const float* __restrict__ src, float* __restrict__ dst,
                              int NC, int sH, int sW, int dH, int dW, int add)
{
    int i = blockIdx.x * blockDim.x + threadIdx.x;
    int tot = NC * dH * dW;
    if (i >= tot) return;
    int x = i % dW;
    int y = (i / dW) % dH;
    int c = i / (dW * dH);
    float fy = (dH > 1) ? (float)y * (float)(sH - 1) / (float)(dH - 1) : 0.f;
    float fx = (dW > 1) ? (float)x * (float)(sW - 1) / (float)(dW - 1) : 0.f;
    int y0 = (int)floorf(fy); int y1 = min(y0 + 1, sH - 1); float wy = fy - (float)y0;
    int x0 = (int)floorf(fx); int x1 = min(x0 + 1, sW - 1); float wx = fx - (float)x0;
    const float* sp = src + (size_t)c * sH * sW;
    float v00 = sp[(size_t)y0*sW + x0], v01 = sp[(size_t)y0*sW + x1];
    float v10 = sp[(size_t)y1*sW + x0], v11 = sp[(size_t)y1*sW + x1];
    float t0 = v00 * (1.f - wy) + v10 * wy;
    float t1 = v01 * (1.f - wy) + v11 * wy;
    float v  = t0 * (1.f - wx) + t1 * wx;
    if (add) dst[i] += v; else dst[i] = v;
}

// ---------------- gather controller params from pred3 ----------------
__global__ void gather_params_kernel(const float* __restrict__ pred3, float* __restrict__ params)
{
    int i = blockIdx.x * blockDim.x + threadIdx.x;
    if (i >= 200*169) return;
    int inst = i / 169, p = i % 169;
    int b = inst / 100, j = inst % 100;
    params[i] = pred3[((size_t)(b*254 + 85 + p)) * (96*160) + j];
}

// ---------------- fused 3-layer dynamic conv MLP ----------------
__global__ void dyn_mlp_kernel(const float* __restrict__ mf, const float* __restrict__ params,
                               float* __restrict__ out)
{
    __shared__ float P[169];
    int inst = blockIdx.x;
    for (int i = threadIdx.x; i < 169; i += blockDim.x) P[i] = params[inst*169 + i];
    __syncthreads();
    int b = inst / 100;
    const int HW = 96*160;
    for (int p = blockIdx.y * blockDim.x + threadIdx.x; p < HW; p += gridDim.y * blockDim.x) {
        int row = p / 160, colx = p % 160;
        float in[10];
        #pragma unroll
        for (int c = 0; c < 8; c++) in[c] = mf[((size_t)(b*8 + c)) * HW + p];
        in[8] = -1.f + 2.f * (float)colx / 159.f;   // xx (cols)
        in[9] = -1.f + 2.f * (float)row  / 95.f;    // yy (rows)
        float h1[8];
        #pragma unroll
        for (int o = 0; o < 8; o++) {
            float s = P[152 + o];
            #pragma unroll
            for (int c = 0; c < 10; c++) s += P[o*10 + c] * in[c];
            h1[o] = fmaxf(s, 0.f);
        }
        float h2[8];
        #pragma unroll
        for (int o = 0; o < 8; o++) {
            float s = P[160 + o];
            #pragma unroll
            for (int c = 0; c < 8; c++) s += P[80 + o*8 + c] * h1[c];
            h2[o] = fmaxf(s, 0.f);
        }
        float s3 = P[168];
        #pragma unroll
        for (int c = 0; c < 8; c++) s3 += P[144 + c] * h2[c];
        out[(size_t)inst * HW + p] = s3;
    }
}

// ---------------- host orchestration ----------------
static void run_conv(const float* in, const float* w, const float* bias, const float* scale,
                     float* out, int N, int CIN, int CO, int H, int W)
{
    dim3 grid((W + 31) / 32, ((H + 7) / 8) * N, (CO + 63) / 64);
    conv3x3_kernel<<<grid, 256>>>(in, w, bias, scale, out, N, CIN, CO, H, W);
}

static int g_gn_slot;  // host-side counter, reset each kernel_launch (deterministic)

static void run_gn(const float* x, float* out, const float* g, const float* b,
                   float* stats_base, int N, int C, int H, int W, int groups, int relu)
{
    int Cg = C / groups;
    int E = Cg * H * W;
    int ng = N * groups;
    float* stats = stats_base + (g_gn_slot++) * 128;
    int slabs = E / 8192; if (slabs < 1) slabs = 1; if (slabs > 64) slabs = 64;
    dim3 gs(slabs, ng);
    gn_stats_kernel<<<gs, 256>>>(x, stats, E);
    int total4 = (N * C * H * W) >> 2;
    gn_apply_kernel<<<(total4 + 255) / 256, 256>>>(x, stats, g, b, out,
                                                   total4, (C * H * W) >> 2, (H * W) >> 2,
                                                   Cg, groups, relu, 1.0f / (float)E);
}

extern "C" void kernel_launch(void* const* d_in, const int* in_sizes, int n_in,
                              void* d_out, int out_size)
{
    const int HS[5] = {96, 48, 24, 12, 6};
    const int WS[5] = {160, 80, 40, 20, 10};

    const float* f[5];
    for (int i = 0; i < 5; i++) f[i] = (const float*)d_in[i];
    const float* head_w     = (const float*)d_in[5];
    const float* head_gn_g  = (const float*)d_in[6];
    const float* head_gn_b  = (const float*)d_in[7];
    const float* head_out_w = (const float*)d_in[8];
    const float* head_out_b = (const float*)d_in[9];
    const float* scales     = (const float*)d_in[10];
    const float* ref_w      = (const float*)d_in[11];
    const float* ref_gn_g   = (const float*)d_in[12];
    const float* ref_gn_b   = (const float*)d_in[13];
    const float* tow_w      = (const float*)d_in[14];
    const float* tow_gn_g   = (const float*)d_in[15];
    const float* tow_gn_b   = (const float*)d_in[16];
    const float* out_w      = (const float*)d_in[17];
    const float* out_gn_g   = (const float*)d_in[18];
    const float* out_gn_b   = (const float*)d_in[19];

    float *bufA, *bufB, *mA, *mB, *mC, *stats, *params, *dyn;
    cudaGetSymbolAddress((void**)&bufA,   g_bufA);
    cudaGetSymbolAddress((void**)&bufB,   g_bufB);
    cudaGetSymbolAddress((void**)&mA,     g_mA);
    cudaGetSymbolAddress((void**)&mB,     g_mB);
    cudaGetSymbolAddress((void**)&mC,     g_mC);
    cudaGetSymbolAddress((void**)&stats,  g_stats);
    cudaGetSymbolAddress((void**)&params, g_params);
    cudaGetSymbolAddress((void**)&dyn,    g_dyn);

    float* out = (float*)d_out;
    g_gn_slot = 0;

    // zero all GN stats slots once (28 GN calls * 128 floats)
    zero_kernel<<<(32*128 + 255) / 256, 256>>>(stats, 32*128);

    // output offsets (pred3..pred7, mask_feats, mask_logits)
    size_t pred_off[5];
    size_t off = 0;
    for (int L = 0; L < 5; L++) {
        pred_off[L] = off;
        off += (size_t)2 * 254 * HS[L] * WS[L];
    }
    size_t mf_off = off;            // 2*8*96*160
    off += (size_t)2 * 8 * 96 * 160;
    size_t ml_off = off;            // 200*192*320

    // ---- head branches (shared weights, 5 levels) ----
    for (int L = 0; L < 5; L++) {
        int H = HS[L], W = WS[L];
        const float* x = f[L];
        for (int i = 0; i < 4; i++) {
            run_conv(x, head_w + (size_t)i * 256 * 256 * 9, nullptr, nullptr,
                     bufA, 2, 256, 256, H, W);
            run_gn(bufA, bufB, head_gn_g + i * 256, head_gn_b + i * 256,
                   stats, 2, 256, H, W, 32, 1);
            x = bufB;
        }
        run_conv(x, head_out_w, head_out_b, scales + L,
                 out + pred_off[L], 2, 256, 254, H, W);
    }

    // ---- mask branch: refine levels 0..2, accumulate at level-0 resolution ----
    for (int i = 0; i < 3; i++) {
        int H = HS[i], W = WS[i];
        run_conv(f[i], ref_w + (size_t)i * 128 * 256 * 9, nullptr, nullptr,
                 mA, 2, 256, 128, H, W);
        if (i == 0) {
            run_gn(mA, mC, ref_gn_g + i * 128, ref_gn_b + i * 128, stats, 2, 128, H, W, 1, 1);
        } else {
            run_gn(mA, mB, ref_gn_g + i * 128, ref_gn_b + i * 128, stats, 2, 128, H, W, 1, 1);
            int tot = 2 * 128 * 96 * 160;
            resize_kernel<<<(tot + 255) / 256, 256>>>(mB, mC, 2 * 128, H, W, 96, 160, 1);
        }
    }
    // ---- tower (4 convs, ping-pong mB/mC with mA as raw) ----
    const float* tx = mC;
    for (int i = 0; i < 4; i++) {
        run_conv(tx, tow_w + (size_t)i * 128 * 128 * 9, nullptr, nullptr,
                 mA, 2, 128, 128, 96, 160);
        float* dst = (i % 2 == 0) ? mB : mC;
        run_gn(mA, dst, tow_gn_g + i * 128, tow_gn_b + i * 128, stats, 2, 128, 96, 160, 1, 1);
        tx = dst;
    }
    // ---- out 1x1 conv -> GN -> relu -> mask_feats (into d_out) ----
    {
        int HW = 96 * 160;
        conv1x1_8_kernel<<<(2 * HW + 255) / 256, 256>>>(tx, out_w, mA, 2, 128, HW);
        run_gn(mA, out + mf_off, out_gn_g, out_gn_b, stats, 2, 8, 96, 160, 1, 1);
    }
    // ---- dynamic conv head ----
    gather_params_kernel<<<(200 * 169 + 255) / 256, 256>>>(out + pred_off[0], params);
    {
        dim3 g(200, 60);
        dyn_mlp_kernel<<<g, 256>>>(out + mf_off, params, dyn);
    }
    {
        int tot = 200 * 192 * 320;
        resize_kernel<<<(tot + 255) / 256, 256>>>(dyn, out + ml_off, 200, 96, 160, 192, 320, 0);
    }
}

// round 5
// speedup vs baseline: 1.6538x; 1.5984x over previous
#include <cuda_runtime.h>
#include <math.h>

// ---------------- static device scratch (no allocation allowed) ----------------
// arena: all 5 levels of a 256-ch feature pyramid, batch 2
#define ARENA_E (2*256*(96*160 + 48*80 + 24*40 + 12*20 + 6*10))   // 10,475,520
#define MAXE_128 (2*128*96*160)
__device__ float g_bufA[ARENA_E];
__device__ float g_bufB[ARENA_E];
__device__ float g_mA[MAXE_128];
__device__ float g_mB[MAXE_128];
__device__ float g_mC[MAXE_128];
__device__ float g_stats[32*128];
__device__ float g_params[200*169];
__device__ float g_dyn[200*96*160];
__device__ float g_wb[589824];   // tf32 "big" packed weights (max 256x256x9)
__device__ float g_ws[589824];   // tf32 "small" residual weights

__device__ __forceinline__ unsigned f2tf32(float x) {
    unsigned r;
    asm("cvt.rna.tf32.f32 %0, %1;" : "=r"(r) : "f"(x));
    return r;
}

#define MMA_TF32(C, a0, a1, a2, a3, b0, b1)                                   \
    asm("mma.sync.aligned.m16n8k8.row.col.f32.tf32.tf32.f32 "                 \
        "{%0,%1,%2,%3}, {%4,%5,%6,%7}, {%8,%9}, {%0,%1,%2,%3};"               \
        : "+f"((C)[0]), "+f"((C)[1]), "+f"((C)[2]), "+f"((C)[3])              \
        : "r"(a0), "r"(a1), "r"(a2), "r"(a3), "r"(b0), "r"(b1))

// ---------------- weight prep: fp32 [CO][CIN][3][3] -> big/small packed ----------------
// packed idx = ((z*nchunk + chunk)*9 + t)*512 + icl*64 + ocl
__global__ void prep_w_kernel(const float* __restrict__ w, float* __restrict__ wb,
                              float* __restrict__ ws, int CO, int CIN, int nz)
{
    int nchunk = CIN >> 3;
    int total = nz * nchunk * 4608;
    int i = blockIdx.x * 256 + threadIdx.x;
    if (i >= total) return;
    int ocl = i & 63;
    int icl = (i >> 6) & 7;
    int t   = (i >> 9) % 9;
    int rest  = i / 4608;
    int chunk = rest % nchunk;
    int z     = rest / nchunk;
    int oc = z * 64 + ocl, ic = chunk * 8 + icl;
    float v = 0.f;
    if (oc < CO) v = w[((size_t)oc * CIN + ic) * 9 + t];
    unsigned bu = f2tf32(v);
    float bf = __uint_as_float(bu);
    unsigned su = f2tf32(v - bf);
    wb[i] = bf;
    ws[i] = __uint_as_float(su);
}

// ---------------- conv3x3 via tf32 mma.sync implicit GEMM (3xTF32 accuracy) --------
// Block: 64 oc x (4 rows x 32 cols) px. 8 warps: warp_m = wid&1 (32 oc),
// warp_n = wid>>1 (one output row, 32 cols). Per warp: 2 m-tiles x 4 n-chunks.
#define CONV_SMEM_BYTES 55296
__global__ void __launch_bounds__(256, 2)
conv3x3_mma_kernel(const float* __restrict__ in, const float* __restrict__ wb,
                   const float* __restrict__ ws, const float* __restrict__ bias,
                   const float* __restrict__ scale_ptr, float* __restrict__ out,
                   int N, int CIN, int CO, int H, int W)
{
    extern __shared__ float sm[];
    float* s_wb = sm;           // [9][8][72]  = 5184
    float* s_ws = sm + 5184;    // [9][8][72]
    float* s_ib = sm + 10368;   // [8][6][36]  = 1728
    float* s_is = sm + 12096;   // [8][6][36]

    const int nchunk = CIN >> 3;
    int tiles_y = (H + 3) >> 2;
    int tx0 = blockIdx.x * 32;
    int ty0 = (blockIdx.y % tiles_y) * 4;
    int n   = blockIdx.y / tiles_y;
    int z   = blockIdx.z;
    int tid = threadIdx.x;
    int lane = tid & 31, wid = tid >> 5;
    int warp_m = wid & 1, warp_n = wid >> 1;
    int g  = lane >> 2;    // 0..7
    int tg = lane & 3;     // 0..3

    float acc[2][4][4];
    #pragma unroll
    for (int mt = 0; mt < 2; mt++)
        #pragma unroll
        for (int nc = 0; nc < 4; nc++)
            #pragma unroll
            for (int k = 0; k < 4; k++) acc[mt][nc][k] = 0.f;

    const float* in_n = in + (size_t)n * CIN * H * W;

    for (int ch = 0; ch < nchunk; ch++) {
        __syncthreads();
        // stage weights (coalesced from packed layout)
        {
            const float* wbp = wb + (size_t)(z * nchunk + ch) * 4608;
            const float* wsp = ws + (size_t)(z * nchunk + ch) * 4608;
            for (int i = tid; i < 4608; i += 256) {
                int t = i >> 9, icl = (i >> 6) & 7, ocl = i & 63;
                int si = (t * 8 + icl) * 72 + ocl;
                s_wb[si] = wbp[i];
                s_ws[si] = wsp[i];
            }
        }
        // stage input tile 8ic x 6row x 34col with halo, split big/small
        {
            const float* ip = in_n + (size_t)(ch * 8) * H * W;
            for (int i = tid; i < 1632; i += 256) {
                int cc = i % 34;
                int rr = (i / 34) % 6;
                int ci = i / 204;
                int gy = ty0 + rr - 1, gx = tx0 + cc - 1;
                float v = 0.f;
                if ((unsigned)gy < (unsigned)H && (unsigned)gx < (unsigned)W)
                    v = ip[(size_t)ci * H * W + (size_t)gy * W + gx];
                unsigned bu = f2tf32(v);
                float bf = __uint_as_float(bu);
                unsigned su = f2tf32(v - bf);
                int si = (ci * 6 + rr) * 36 + cc;
                s_ib[si] = bf;
                s_is[si] = __uint_as_float(su);
            }
        }
        __syncthreads();

        #pragma unroll
        for (int t = 0; t < 9; t++) {
            const int ky = t / 3, kx = t % 3;
            unsigned ab[2][4], aS[2][4];
            #pragma unroll
            for (int mt = 0; mt < 2; mt++) {
                int ocl = warp_m * 32 + mt * 16 + g;
                const float* p0 = &s_wb[(t * 8 + tg) * 72 + ocl];
                const float* p1 = &s_wb[(t * 8 + tg + 4) * 72 + ocl];
                ab[mt][0] = __float_as_uint(p0[0]);
                ab[mt][1] = __float_as_uint(p0[8]);
                ab[mt][2] = __float_as_uint(p1[0]);
                ab[mt][3] = __float_as_uint(p1[8]);
                const float* q0 = &s_ws[(t * 8 + tg) * 72 + ocl];
                const float* q1 = &s_ws[(t * 8 + tg + 4) * 72 + ocl];
                aS[mt][0] = __float_as_uint(q0[0]);
                aS[mt][1] = __float_as_uint(q0[8]);
                aS[mt][2] = __float_as_uint(q1[0]);
                aS[mt][3] = __float_as_uint(q1[8]);
            }
            int rrow = warp_n + ky;
            #pragma unroll
            for (int nc = 0; nc < 4; nc++) {
                int ccol = nc * 8 + g + kx;
                unsigned bb0 = __float_as_uint(s_ib[(tg * 6 + rrow) * 36 + ccol]);
                unsigned bb1 = __float_as_uint(s_ib[((tg + 4) * 6 + rrow) * 36 + ccol]);
                unsigned bs0 = __float_as_uint(s_is[(tg * 6 + rrow) * 36 + ccol]);
                unsigned bs1 = __float_as_uint(s_is[((tg + 4) * 6 + rrow) * 36 + ccol]);
                #pragma unroll
                for (int mt = 0; mt < 2; mt++) {
                    MMA_TF32(acc[mt][nc], ab[mt][0], ab[mt][1], ab[mt][2], ab[mt][3], bb0, bb1);
                    MMA_TF32(acc[mt][nc], ab[mt][0], ab[mt][1], ab[mt][2], ab[mt][3], bs0, bs1);
                    MMA_TF32(acc[mt][nc], aS[mt][0], aS[mt][1], aS[mt][2], aS[mt][3], bb0, bb1);
                }
            }
        }
    }

    // epilogue
    float sc = scale_ptr ? *scale_ptr : 1.0f;
    int gy = ty0 + warp_n;
    if (gy < H) {
        #pragma unroll
        for (int mt = 0; mt < 2; mt++) {
            #pragma unroll
            for (int nc = 0; nc < 4; nc++) {
                int gx = tx0 + nc * 8 + 2 * tg;
                int oc = z * 64 + warp_m * 32 + mt * 16 + g;
                if (oc < CO) {
                    float b0 = bias ? bias[oc] : 0.f;
                    size_t base = ((size_t)(n * CO + oc) * H + gy) * W;
                    if (gx < W)     out[base + gx]     = acc[mt][nc][0] * sc + b0;
                    if (gx + 1 < W) out[base + gx + 1] = acc[mt][nc][1] * sc + b0;
                }
                int oc2 = oc + 8;
                if (oc2 < CO) {
                    float b2 = bias ? bias[oc2] : 0.f;
                    size_t base2 = ((size_t)(n * CO + oc2) * H + gy) * W;
                    if (gx < W)     out[base2 + gx]     = acc[mt][nc][2] * sc + b2;
                    if (gx + 1 < W) out[base2 + gx + 1] = acc[mt][nc][3] * sc + b2;
                }
            }
        }
    }
}

// ---------------- GroupNorm: zero / stats / apply ----------------
__global__ void zero_kernel(float* p, int n)
{
    int i = blockIdx.x * blockDim.x + threadIdx.x;
    if (i < n) p[i] = 0.f;
}

__global__ void gn_stats_kernel(const float* __restrict__ x, float* __restrict__ stats, int E)
{
    int gi = blockIdx.y;
    const float4* p = (const float4*)(x + (size_t)gi * E);
    int E4 = E >> 2;
    float s1 = 0.f, s2 = 0.f;
    for (int i = blockIdx.x * blockDim.x + threadIdx.x; i < E4; i += gridDim.x * blockDim.x) {
        float4 v = p[i];
        s1 += v.x + v.y + v.z + v.w;
        s2 += v.x*v.x + v.y*v.y + v.z*v.z + v.w*v.w;
    }
    #pragma unroll
    for (int o = 16; o; o >>= 1) {
        s1 += __shfl_down_sync(0xffffffffu, s1, o);
        s2 += __shfl_down_sync(0xffffffffu, s2, o);
    }
    __shared__ float r1[32], r2[32];
    int w = threadIdx.x >> 5, l = threadIdx.x & 31;
    if (l == 0) { r1[w] = s1; r2[w] = s2; }
    __syncthreads();
    if (w == 0) {
        int nw = blockDim.x >> 5;
        s1 = (l < nw) ? r1[l] : 0.f;
        s2 = (l < nw) ? r2[l] : 0.f;
        #pragma unroll
        for (int o = 16; o; o >>= 1) {
            s1 += __shfl_down_sync(0xffffffffu, s1, o);
            s2 += __shfl_down_sync(0xffffffffu, s2, o);
        }
        if (l == 0) {
            atomicAdd(&stats[gi*2],   s1);
            atomicAdd(&stats[gi*2+1], s2);
        }
    }
}

__global__ void gn_apply_kernel(const float* __restrict__ x, const float* __restrict__ stats,
                                const float* __restrict__ gg, const float* __restrict__ bb,
                                float* __restrict__ out,
                                int total4, int CHW4, int HW4, int Cg, int groups, int relu,
                                float invE)
{
    int i = blockIdx.x * blockDim.x + threadIdx.x;
    if (i >= total4) return;
    int n = i / CHW4;
    int c = (i % CHW4) / HW4;
    int gi = n * groups + c / Cg;
    float s1 = stats[gi*2], s2 = stats[gi*2+1];
    float mu  = s1 * invE;
    float var = s2 * invE - mu * mu;
    float rs  = rsqrtf(var + 1e-5f);
    float a = rs * gg[c];
    float b = bb[c] - mu * a;
    float4 v = ((const float4*)x)[i];
    v.x = v.x * a + b; v.y = v.y * a + b; v.z = v.z * a + b; v.w = v.w * a + b;
    if (relu) {
        v.x = fmaxf(v.x, 0.f); v.y = fmaxf(v.y, 0.f);
        v.z = fmaxf(v.z, 0.f); v.w = fmaxf(v.w, 0.f);
    }
    ((float4*)out)[i] = v;
}

// ---------------- 1x1 conv 128 -> 8 ----------------
__global__ void conv1x1_8_kernel(const float* __restrict__ in, const float* __restrict__ w,
                                 float* __restrict__ out, int N, int CIN, int HW)
{
    __shared__ float sw[8*128];
    for (int i = threadIdx.x; i < 8*CIN; i += blockDim.x) sw[i] = w[i];
    __syncthreads();
    int p = blockIdx.x * blockDim.x + threadIdx.x;
    if (p >= N * HW) return;
    int n = p / HW, pp = p % HW;
    const float* ip = in + (size_t)n * CIN * HW + pp;
    float a[8] = {0,0,0,0,0,0,0,0};
    for (int c = 0; c < CIN; c++) {
        float v = ip[(size_t)c * HW];
        #pragma unroll
        for (int o = 0; o < 8; o++) a[o] += sw[o*CIN + c] * v;
    }
    #pragma unroll
    for (int o = 0; o < 8; o++)
        out[((size_t)(n*8 + o)) * HW + pp] = a[o];
}

// ---------------- bilinear resize (align-corners linspace), optional add ----------------
__global__ void resize_kernel(const float* __restrict__ src, float* __restrict__ dst,
                              int NC, int sH, int sW, int dH, int dW, int add)
{
    int i = blockIdx.x * blockDim.x + threadIdx.x;
    int tot = NC * dH * dW;
    if (i >= tot) return;
    int x = i % dW;
    int y = (i / dW) % dH;
    int c = i / (dW * dH);
    float fy = (dH > 1) ? (float)y * (float)(sH - 1) / (float)(dH - 1) : 0.f;
    float fx = (dW > 1) ? (float)x * (float)(sW - 1) / (float)(dW - 1) : 0.f;
    int y0 = (int)floorf(fy); int y1 = min(y0 + 1, sH - 1); float wy = fy - (float)y0;
    int x0 = (int)floorf(fx); int x1 = min(x0 + 1, sW - 1); float wx = fx - (float)x0;
    const float* sp = src + (size_t)c * sH * sW;
    float v00 = sp[(size_t)y0*sW + x0], v01 = sp[(size_t)y0*sW + x1];
    float v10 = sp[(size_t)y1*sW + x0], v11 = sp[(size_t)y1*sW + x1];
    float t0 = v00 * (1.f - wy) + v10 * wy;
    float t1 = v01 * (1.f - wy) + v11 * wy;
    float v  = t0 * (1.f - wx) + t1 * wx;
    if (add) dst[i] += v; else dst[i] = v;
}

// ---------------- gather controller params from pred3 ----------------
__global__ void gather_params_kernel(const float* __restrict__ pred3, float* __restrict__ params)
{
    int i = blockIdx.x * blockDim.x + threadIdx.x;
    if (i >= 200*169) return;
    int inst = i / 169, p = i % 169;
    int b = inst / 100, j = inst % 100;
    params[i] = pred3[((size_t)(b*254 + 85 + p)) * (96*160) + j];
}

// ---------------- fused 3-layer dynamic conv MLP ----------------
__global__ void dyn_mlp_kernel(const float* __restrict__ mf, const float* __restrict__ params,
                               float* __restrict__ out)
{
    __shared__ float P[169];
    int inst = blockIdx.x;
    for (int i = threadIdx.x; i < 169; i += blockDim.x) P[i] = params[inst*169 + i];
    __syncthreads();
    int b = inst / 100;
    const int HW = 96*160;
    for (int p = blockIdx.y * blockDim.x + threadIdx.x; p < HW; p += gridDim.y * blockDim.x) {
        int row = p / 160, colx = p % 160;
        float in[10];
        #pragma unroll
        for (int c = 0; c < 8; c++) in[c] = mf[((size_t)(b*8 + c)) * HW + p];
        in[8] = -1.f + 2.f * (float)colx / 159.f;
        in[9] = -1.f + 2.f * (float)row  / 95.f;
        float h1[8];
        #pragma unroll
        for (int o = 0; o < 8; o++) {
            float s = P[152 + o];
            #pragma unroll
            for (int c = 0; c < 10; c++) s += P[o*10 + c] * in[c];
            h1[o] = fmaxf(s, 0.f);
        }
        float h2[8];
        #pragma unroll
        for (int o = 0; o < 8; o++) {
            float s = P[160 + o];
            #pragma unroll
            for (int c = 0; c < 8; c++) s += P[80 + o*8 + c] * h1[c];
            h2[o] = fmaxf(s, 0.f);
        }
        float s3 = P[168];
        #pragma unroll
        for (int c = 0; c < 8; c++) s3 += P[144 + c] * h2[c];
        out[(size_t)inst * HW + p] = s3;
    }
}

// ---------------- host orchestration ----------------
static void run_prep(const float* w, float* wb, float* ws, int CO, int CIN)
{
    int nz = (CO + 63) / 64;
    int total = nz * (CIN >> 3) * 4608;
    prep_w_kernel<<<(total + 255) / 256, 256>>>(w, wb, ws, CO, CIN, nz);
}

static void run_conv(const float* in, const float* wb, const float* ws,
                     const float* bias, const float* scale,
                     float* out, int N, int CIN, int CO, int H, int W)
{
    dim3 grid((W + 31) / 32, ((H + 3) / 4) * N, (CO + 63) / 64);
    conv3x3_mma_kernel<<<grid, 256, CONV_SMEM_BYTES>>>(in, wb, ws, bias, scale,
                                                       out, N, CIN, CO, H, W);
}

static int g_gn_slot;

static void run_gn(const float* x, float* out, const float* g, const float* b,
                   float* stats_base, int N, int C, int H, int W, int groups, int relu)
{
    int Cg = C / groups;
    int E = Cg * H * W;
    int ng = N * groups;
    float* stats = stats_base + (g_gn_slot++) * 128;
    int slabs = E / 8192; if (slabs < 1) slabs = 1; if (slabs > 64) slabs = 64;
    dim3 gs(slabs, ng);
    gn_stats_kernel<<<gs, 256>>>(x, stats, E);
    int total4 = (N * C * H * W) >> 2;
    gn_apply_kernel<<<(total4 + 255) / 256, 256>>>(x, stats, g, b, out,
                                                   total4, (C * H * W) >> 2, (H * W) >> 2,
                                                   Cg, groups, relu, 1.0f / (float)E);
}

extern "C" void kernel_launch(void* const* d_in, const int* in_sizes, int n_in,
                              void* d_out, int out_size)
{
    const int HS[5] = {96, 48, 24, 12, 6};
    const int WS[5] = {160, 80, 40, 20, 10};

    const float* f[5];
    for (int i = 0; i < 5; i++) f[i] = (const float*)d_in[i];
    const float* head_w     = (const float*)d_in[5];
    const float* head_gn_g  = (const float*)d_in[6];
    const float* head_gn_b  = (const float*)d_in[7];
    const float* head_out_w = (const float*)d_in[8];
    const float* head_out_b = (const float*)d_in[9];
    const float* scales     = (const float*)d_in[10];
    const float* ref_w      = (const float*)d_in[11];
    const float* ref_gn_g   = (const float*)d_in[12];
    const float* ref_gn_b   = (const float*)d_in[13];
    const float* tow_w      = (const float*)d_in[14];
    const float* tow_gn_g   = (const float*)d_in[15];
    const float* tow_gn_b   = (const float*)d_in[16];
    const float* out_w      = (const float*)d_in[17];
    const float* out_gn_g   = (const float*)d_in[18];
    const float* out_gn_b   = (const float*)d_in[19];

    float *bufA, *bufB, *mA, *mB, *mC, *stats, *params, *dyn, *wb, *ws;
    cudaGetSymbolAddress((void**)&bufA,   g_bufA);
    cudaGetSymbolAddress((void**)&bufB,   g_bufB);
    cudaGetSymbolAddress((void**)&mA,     g_mA);
    cudaGetSymbolAddress((void**)&mB,     g_mB);
    cudaGetSymbolAddress((void**)&mC,     g_mC);
    cudaGetSymbolAddress((void**)&stats,  g_stats);
    cudaGetSymbolAddress((void**)&params, g_params);
    cudaGetSymbolAddress((void**)&dyn,    g_dyn);
    cudaGetSymbolAddress((void**)&wb,     g_wb);
    cudaGetSymbolAddress((void**)&ws,     g_ws);

    cudaFuncSetAttribute(conv3x3_mma_kernel,
                         cudaFuncAttributeMaxDynamicSharedMemorySize, CONV_SMEM_BYTES);

    float* out = (float*)d_out;
    g_gn_slot = 0;

    zero_kernel<<<(32*128 + 255) / 256, 256>>>(stats, 32*128);

    // output offsets
    size_t pred_off[5];
    size_t off = 0;
    for (int L = 0; L < 5; L++) {
        pred_off[L] = off;
        off += (size_t)2 * 254 * HS[L] * WS[L];
    }
    size_t mf_off = off;
    off += (size_t)2 * 8 * 96 * 160;
    size_t ml_off = off;

    // per-level arena offsets (256-channel features)
    size_t lo[5];
    size_t a = 0;
    for (int L = 0; L < 5; L++) { lo[L] = a; a += (size_t)2 * 256 * HS[L] * WS[L]; }

    // ---- head branches: layer-outer so each weight prep is reused across 5 levels ----
    for (int i = 0; i < 4; i++) {
        run_prep(head_w + (size_t)i * 256 * 256 * 9, wb, ws, 256, 256);
        for (int L = 0; L < 5; L++) {
            const float* src = (i == 0) ? f[L] : (bufB + lo[L]);
            run_conv(src, wb, ws, nullptr, nullptr, bufA + lo[L], 2, 256, 256, HS[L], WS[L]);
            run_gn(bufA + lo[L], bufB + lo[L], head_gn_g + i * 256, head_gn_b + i * 256,
                   stats, 2, 256, HS[L], WS[L], 32, 1);
        }
    }
    run_prep(head_out_w, wb, ws, 254, 256);
    for (int L = 0; L < 5; L++) {
        run_conv(bufB + lo[L], wb, ws, head_out_b, scales + L,
                 out + pred_off[L], 2, 256, 254, HS[L], WS[L]);
    }

    // ---- mask branch: refine levels 0..2, accumulate at level-0 resolution ----
    for (int i = 0; i < 3; i++) {
        int H = HS[i], W = WS[i];
        run_prep(ref_w + (size_t)i * 128 * 256 * 9, wb, ws, 128, 256);
        run_conv(f[i], wb, ws, nullptr, nullptr, mA, 2, 256, 128, H, W);
        if (i == 0) {
            run_gn(mA, mC, ref_gn_g + i * 128, ref_gn_b + i * 128, stats, 2, 128, H, W, 1, 1);
        } else {
            run_gn(mA, mB, ref_gn_g + i * 128, ref_gn_b + i * 128, stats, 2, 128, H, W, 1, 1);
            int tot = 2 * 128 * 96 * 160;
            resize_kernel<<<(tot + 255) / 256, 256>>>(mB, mC, 2 * 128, H, W, 96, 160, 1);
        }
    }
    // ---- tower ----
    const float* tx = mC;
    for (int i = 0; i < 4; i++) {
        run_prep(tow_w + (size_t)i * 128 * 128 * 9, wb, ws, 128, 128);
        run_conv(tx, wb, ws, nullptr, nullptr, mA, 2, 128, 128, 96, 160);
        float* dst = (i % 2 == 0) ? mB : mC;
        run_gn(mA, dst, tow_gn_g + i * 128, tow_gn_b + i * 128, stats, 2, 128, 96, 160, 1, 1);
        tx = dst;
    }
    // ---- out 1x1 conv -> GN -> relu -> mask_feats ----
    {
        int HW = 96 * 160;
        conv1x1_8_kernel<<<(2 * HW + 255) / 256, 256>>>(tx, out_w, mA, 2, 128, HW);
        run_gn(mA, out + mf_off, out_gn_g, out_gn_b, stats, 2, 8, 96, 160, 1, 1);
    }
    // ---- dynamic conv head ----
    gather_params_kernel<<<(200 * 169 + 255) / 256, 256>>>(out + pred_off[0], params);
    {
        dim3 g(200, 60);
        dyn_mlp_kernel<<<g, 256>>>(out + mf_off, params, dyn);
    }
    {
        int tot = 200 * 192 * 320;
        resize_kernel<<<(tot + 255) / 256, 256>>>(dyn, out + ml_off, 200, 96, 160, 192, 320, 0);
    }
}

// round 7
// speedup vs baseline: 2.9743x; 1.7985x over previous
#include <cuda_runtime.h>
#include <cuda_bf16.h>
#include <math.h>

// ---------------- static device scratch (no allocation allowed) ----------------
#define ARENA_E (2*256*(96*160 + 48*80 + 24*40 + 12*20 + 6*10))   // 10,475,520
#define MAXE_128 (2*128*96*160)
__device__ float g_bufA[ARENA_E];
__device__ float g_bufB[ARENA_E];
__device__ float g_mA[MAXE_128];
__device__ float g_mB[MAXE_128];
__device__ float g_mC[MAXE_128];
__device__ float g_stats[32*128];
__device__ float g_params[200*169];
__device__ float g_dyn[200*96*160];
__device__ unsigned g_wb[294912];   // packed bf16x2 "big" weights (max 4 z * 16 chunks * 4608)
__device__ unsigned g_ws[294912];   // packed bf16x2 "small" residual weights

#define MMA_BF16(C, a0, a1, a2, a3, b0, b1)                                   \
    asm("mma.sync.aligned.m16n8k16.row.col.f32.bf16.bf16.f32 "                \
        "{%0,%1,%2,%3}, {%4,%5,%6,%7}, {%8,%9}, {%0,%1,%2,%3};"               \
        : "+f"((C)[0]), "+f"((C)[1]), "+f"((C)[2]), "+f"((C)[3])              \
        : "r"(a0), "r"(a1), "r"(a2), "r"(a3), "r"(b0), "r"(b1))

__device__ __forceinline__ unsigned pack_bf16_split(float v0, float v1, unsigned& small)
{
    __nv_bfloat16 b0 = __float2bfloat16_rn(v0);
    __nv_bfloat16 b1 = __float2bfloat16_rn(v1);
    float r0 = v0 - __bfloat162float(b0);
    float r1 = v1 - __bfloat162float(b1);
    __nv_bfloat16 s0 = __float2bfloat16_rn(r0);
    __nv_bfloat16 s1 = __float2bfloat16_rn(r1);
    small = ((unsigned)__bfloat16_as_ushort(s1) << 16) | (unsigned)__bfloat16_as_ushort(s0);
    return ((unsigned)__bfloat16_as_ushort(b1) << 16) | (unsigned)__bfloat16_as_ushort(b0);
}

// ---------------- weight prep: fp32 [CO][CIN][3][3] -> packed bf16x2 big/small ------
// word idx = ((z*nchunk + ch)*9 + t)*512 + icpair*64 + ocl ; word = {ic even, ic odd}
__global__ void prep_w_kernel(const float* __restrict__ w, unsigned* __restrict__ wb,
                              unsigned* __restrict__ ws, int CO, int CIN, int nz)
{
    int nchunk = CIN >> 4;
    int total = nz * nchunk * 4608;
    int i = blockIdx.x * 256 + threadIdx.x;
    if (i >= total) return;
    int ocl = i & 63;
    int p   = (i >> 6) & 7;
    int t   = (i >> 9) % 9;
    int rest  = i / 4608;
    int ch    = rest % nchunk;
    int z     = rest / nchunk;
    int oc = z * 64 + ocl, ic = ch * 16 + 2 * p;
    float v0 = 0.f, v1 = 0.f;
    if (oc < CO) {
        v0 = w[((size_t)oc * CIN + ic) * 9 + t];
        v1 = w[((size_t)oc * CIN + ic + 1) * 9 + t];
    }
    unsigned sm;
    unsigned bg = pack_bf16_split(v0, v1, sm);
    wb[i] = bg;
    ws[i] = sm;
}

// ---------------- conv3x3 via bf16 m16n8k16 mma.sync (3-term split) ----------------
// Block: 64 oc x (4 rows x 32 cols) px. 8 warps: warp_m = wid&1 (32 oc),
// warp_n = wid>>1 (one output row, 32 cols). Per warp: 2 m-tiles x 4 n-chunks.
#define CONV_SMEM_BYTES 55296
__global__ void __launch_bounds__(256, 2)
conv3x3_mma_kernel(const float* __restrict__ in, const unsigned* __restrict__ wb,
                   const unsigned* __restrict__ ws, const float* __restrict__ bias,
                   const float* __restrict__ scale_ptr, float* __restrict__ out,
                   int N, int CIN, int CO, int H, int W)
{
    extern __shared__ unsigned sm[];
    unsigned* s_wb = sm;            // [9][8][72]  = 5184 words
    unsigned* s_ws = sm + 5184;     // [9][8][72]
    unsigned* s_ib = sm + 10368;    // [8][6][36]  = 1728 words (ic-pair packed)
    unsigned* s_is = sm + 12096;    // [8][6][36]

    const int nchunk = CIN >> 4;    // 16 input channels per chunk
    int tiles_y = (H + 3) >> 2;
    int tx0 = blockIdx.x * 32;
    int ty0 = (blockIdx.y % tiles_y) * 4;
    int n   = blockIdx.y / tiles_y;
    int z   = blockIdx.z;
    int tid = threadIdx.x;
    int lane = tid & 31, wid = tid >> 5;
    int warp_m = wid & 1, warp_n = wid >> 1;
    int g  = lane >> 2;    // 0..7
    int tg = lane & 3;     // 0..3

    float acc[2][4][4];
    #pragma unroll
    for (int mt = 0; mt < 2; mt++)
        #pragma unroll
        for (int nc = 0; nc < 4; nc++)
            #pragma unroll
            for (int k = 0; k < 4; k++) acc[mt][nc][k] = 0.f;

    const float* in_n = in + (size_t)n * CIN * H * W;

    for (int ch = 0; ch < nchunk; ch++) {
        __syncthreads();
        // stage packed weights
        {
            const unsigned* wbp = wb + (size_t)(z * nchunk + ch) * 4608;
            const unsigned* wsp = ws + (size_t)(z * nchunk + ch) * 4608;
            for (int i = tid; i < 4608; i += 256) {
                int t = i >> 9, p = (i >> 6) & 7, ocl = i & 63;
                int si = (t * 8 + p) * 72 + ocl;
                s_wb[si] = wbp[i];
                s_ws[si] = wsp[i];
            }
        }
        // stage input tile: 8 ic-pairs x 6 rows x 34 cols with halo, bf16 split+pack
        {
            const float* ip = in_n + (size_t)(ch * 16) * H * W;
            for (int i = tid; i < 1632; i += 256) {
                int cc = i % 34;
                int rr = (i / 34) % 6;
                int p  = i / 204;
                int gy = ty0 + rr - 1, gx = tx0 + cc - 1;
                float v0 = 0.f, v1 = 0.f;
                if ((unsigned)gy < (unsigned)H && (unsigned)gx < (unsigned)W) {
                    size_t base = (size_t)(2 * p) * H * W + (size_t)gy * W + gx;
                    v0 = ip[base];
                    v1 = ip[base + (size_t)H * W];
                }
                unsigned smv;
                unsigned bgv = pack_bf16_split(v0, v1, smv);
                int si = (p * 6 + rr) * 36 + cc;
                s_ib[si] = bgv;
                s_is[si] = smv;
            }
        }
        __syncthreads();

        #pragma unroll
        for (int t = 0; t < 9; t++) {
            const int ky = t / 3, kx = t % 3;
            unsigned ab[2][4], aS[2][4];
            #pragma unroll
            for (int mt = 0; mt < 2; mt++) {
                int ocl = warp_m * 32 + mt * 16 + g;
                const unsigned* p0 = &s_wb[(t * 8 + tg) * 72 + ocl];
                const unsigned* p1 = &s_wb[(t * 8 + tg + 4) * 72 + ocl];
                ab[mt][0] = p0[0];
                ab[mt][1] = p0[8];
                ab[mt][2] = p1[0];
                ab[mt][3] = p1[8];
                const unsigned* q0 = &s_ws[(t * 8 + tg) * 72 + ocl];
                const unsigned* q1 = &s_ws[(t * 8 + tg + 4) * 72 + ocl];
                aS[mt][0] = q0[0];
                aS[mt][1] = q0[8];
                aS[mt][2] = q1[0];
                aS[mt][3] = q1[8];
            }
            int rrow = warp_n + ky;
            #pragma unroll
            for (int nc = 0; nc < 4; nc++) {
                int ccol = nc * 8 + g + kx;
                unsigned bb0 = s_ib[(tg * 6 + rrow) * 36 + ccol];
                unsigned bb1 = s_ib[((tg + 4) * 6 + rrow) * 36 + ccol];
                unsigned bs0 = s_is[(tg * 6 + rrow) * 36 + ccol];
                unsigned bs1 = s_is[((tg + 4) * 6 + rrow) * 36 + ccol];
                #pragma unroll
                for (int mt = 0; mt < 2; mt++) {
                    MMA_BF16(acc[mt][nc], ab[mt][0], ab[mt][1], ab[mt][2], ab[mt][3], bb0, bb1);
                    MMA_BF16(acc[mt][nc], ab[mt][0], ab[mt][1], ab[mt][2], ab[mt][3], bs0, bs1);
                    MMA_BF16(acc[mt][nc], aS[mt][0], aS[mt][1], aS[mt][2], aS[mt][3], bb0, bb1);
                }
            }
        }
    }

    // epilogue (D layout: c0=D[g][2tg], c1=D[g][2tg+1], c2=D[g+8][2tg], c3=D[g+8][2tg+1])
    float sc = scale_ptr ? *scale_ptr : 1.0f;
    int gy = ty0 + warp_n;
    if (gy < H) {
        #pragma unroll
        for (int mt = 0; mt < 2; mt++) {
            #pragma unroll
            for (int nc = 0; nc < 4; nc++) {
                int gx = tx0 + nc * 8 + 2 * tg;
                int oc = z * 64 + warp_m * 32 + mt * 16 + g;
                if (oc < CO) {
                    float b0 = bias ? bias[oc] : 0.f;
                    size_t base = ((size_t)(n * CO + oc) * H + gy) * W;
                    if (gx < W)     out[base + gx]     = acc[mt][nc][0] * sc + b0;
                    if (gx + 1 < W) out[base + gx + 1] = acc[mt][nc][1] * sc + b0;
                }
                int oc2 = oc + 8;
                if (oc2 < CO) {
                    float b2 = bias ? bias[oc2] : 0.f;
                    size_t base2 = ((size_t)(n * CO + oc2) * H + gy) * W;
                    if (gx < W)     out[base2 + gx]     = acc[mt][nc][2] * sc + b2;
                    if (gx + 1 < W) out[base2 + gx + 1] = acc[mt][nc][3] * sc + b2;
                }
            }
        }
    }
}

// ---------------- GroupNorm: zero / stats / apply ----------------
__global__ void zero_kernel(float* p, int n)
{
    int i = blockIdx.x * blockDim.x + threadIdx.x;
    if (i < n) p[i] = 0.f;
}

__global__ void gn_stats_kernel(const float* __restrict__ x, float* __restrict__ stats, int E)
{
    int gi = blockIdx.y;
    const float4* p = (const float4*)(x + (size_t)gi * E);
    int E4 = E >> 2;
    float s1 = 0.f, s2 = 0.f;
    for (int i = blockIdx.x * blockDim.x + threadIdx.x; i < E4; i += gridDim.x * blockDim.x) {
        float4 v = p[i];
        s1 += v.x + v.y + v.z + v.w;
        s2 += v.x*v.x + v.y*v.y + v.z*v.z + v.w*v.w;
    }
    #pragma unroll
    for (int o = 16; o; o >>= 1) {
        s1 += __shfl_down_sync(0xffffffffu, s1, o);
        s2 += __shfl_down_sync(0xffffffffu, s2, o);
    }
    __shared__ float r1[32], r2[32];
    int w = threadIdx.x >> 5, l = threadIdx.x & 31;
    if (l == 0) { r1[w] = s1; r2[w] = s2; }
    __syncthreads();
    if (w == 0) {
        int nw = blockDim.x >> 5;
        s1 = (l < nw) ? r1[l] : 0.f;
        s2 = (l < nw) ? r2[l] : 0.f;
        #pragma unroll
        for (int o = 16; o; o >>= 1) {
            s1 += __shfl_down_sync(0xffffffffu, s1, o);
            s2 += __shfl_down_sync(0xffffffffu, s2, o);
        }
        if (l == 0) {
            atomicAdd(&stats[gi*2],   s1);
            atomicAdd(&stats[gi*2+1], s2);
        }
    }
}

__global__ void gn_apply_kernel(const float* __restrict__ x, const float* __restrict__ stats,
                                const float* __restrict__ gg, const float* __restrict__ bb,
                                float* __restrict__ out,
                                int total4, int CHW4, int HW4, int Cg, int groups, int relu,
                                float invE)
{
    int i = blockIdx.x * blockDim.x + threadIdx.x;
    if (i >= total4) return;
    int n = i / CHW4;
    int c = (i % CHW4) / HW4;
    int gi = n * groups + c / Cg;
    float s1 = stats[gi*2], s2 = stats[gi*2+1];
    float mu  = s1 * invE;
    float var = s2 * invE - mu * mu;
    float rs  = rsqrtf(var + 1e-5f);
    float a = rs * gg[c];
    float b = bb[c] - mu * a;
    float4 v = ((const float4*)x)[i];
    v.x = v.x * a + b; v.y = v.y * a + b; v.z = v.z * a + b; v.w = v.w * a + b;
    if (relu) {
        v.x = fmaxf(v.x, 0.f); v.y = fmaxf(v.y, 0.f);
        v.z = fmaxf(v.z, 0.f); v.w = fmaxf(v.w, 0.f);
    }
    ((float4*)out)[i] = v;
}

// ---------------- 1x1 conv 128 -> 8 ----------------
__global__ void conv1x1_8_kernel(const float* __restrict__ in, const float* __restrict__ w,
                                 float* __restrict__ out, int N, int CIN, int HW)
{
    __shared__ float sw[8*128];
    for (int i = threadIdx.x; i < 8*CIN; i += blockDim.x) sw[i] = w[i];
    __syncthreads();
    int p = blockIdx.x * blockDim.x + threadIdx.x;
    if (p >= N * HW) return;
    int n = p / HW, pp = p % HW;
    const float* ip = in + (size_t)n * CIN * HW + pp;
    float a[8] = {0,0,0,0,0,0,0,0};
    for (int c = 0; c < CIN; c++) {
        float v = ip[(size_t)c * HW];
        #pragma unroll
        for (int o = 0; o < 8; o++) a[o] += sw[o*CIN + c] * v;
    }
    #pragma unroll
    for (int o = 0; o < 8; o++)
        out[((size_t)(n*8 + o)) * HW + pp] = a[o];
}

// ---------------- bilinear resize (align-corners linspace), optional add ----------------
__global__ void resize_kernel(const float* __restrict__ src, float* __restrict__ dst,
                              int NC, int sH, int sW, int dH, int dW, int add)
{
    int i = blockIdx.x * blockDim.x + threadIdx.x;
    int tot = NC * dH * dW;
    if (i >= tot) return;
    int x = i % dW;
    int y = (i / dW) % dH;
    int c = i / (dW * dH);
    float fy = (dH > 1) ? (float)y * (float)(sH - 1) / (float)(dH - 1) : 0.f;
    float fx = (dW > 1) ? (float)x * (float)(sW - 1) / (float)(dW - 1) : 0.f;
    int y0 = (int)floorf(fy); int y1 = min(y0 + 1, sH - 1); float wy = fy - (float)y0;
    int x0 = (int)floorf(fx); int x1 = min(x0 + 1, sW - 1); float wx = fx - (float)x0;
    const float* sp = src + (size_t)c * sH * sW;
    float v00 = sp[(size_t)y0*sW + x0], v01 = sp[(size_t)y0*sW + x1];
    float v10 = sp[(size_t)y1*sW + x0], v11 = sp[(size_t)y1*sW + x1];
    float t0 = v00 * (1.f - wy) + v10 * wy;
    float t1 = v01 * (1.f - wy) + v11 * wy;
    float v  = t0 * (1.f - wx) + t1 * wx;
    if (add) dst[i] += v; else dst[i] = v;
}

// ---------------- gather controller params from pred3 ----------------
__global__ void gather_params_kernel(const float* __restrict__ pred3, float* __restrict__ params)
{
    int i = blockIdx.x * blockDim.x + threadIdx.x;
    if (i >= 200*169) return;
    int inst = i / 169, p = i % 169;
    int b = inst / 100, j = inst % 100;
    params[i] = pred3[((size_t)(b*254 + 85 + p)) * (96*160) + j];
}

// ---------------- fused 3-layer dynamic conv MLP ----------------
__global__ void dyn_mlp_kernel(const float* __restrict__ mf, const float* __restrict__ params,
                               float* __restrict__ out)
{
    __shared__ float P[169];
    int inst = blockIdx.x;
    for (int i = threadIdx.x; i < 169; i += blockDim.x) P[i] = params[inst*169 + i];
    __syncthreads();
    int b = inst / 100;
    const int HW = 96*160;
    for (int p = blockIdx.y * blockDim.x + threadIdx.x; p < HW; p += gridDim.y * blockDim.x) {
        int row = p / 160, colx = p % 160;
        float in[10];
        #pragma unroll
        for (int c = 0; c < 8; c++) in[c] = mf[((size_t)(b*8 + c)) * HW + p];
        in[8] = -1.f + 2.f * (float)colx / 159.f;
        in[9] = -1.f + 2.f * (float)row  / 95.f;
        float h1[8];
        #pragma unroll
        for (int o = 0; o < 8; o++) {
            float s = P[152 + o];
            #pragma unroll
            for (int c = 0; c < 10; c++) s += P[o*10 + c] * in[c];
            h1[o] = fmaxf(s, 0.f);
        }
        float h2[8];
        #pragma unroll
        for (int o = 0; o < 8; o++) {
            float s = P[160 + o];
            #pragma unroll
            for (int c = 0; c < 8; c++) s += P[80 + o*8 + c] * h1[c];
            h2[o] = fmaxf(s, 0.f);
        }
        float s3 = P[168];
        #pragma unroll
        for (int c = 0; c < 8; c++) s3 += P[144 + c] * h2[c];
        out[(size_t)inst * HW + p] = s3;
    }
}

// ---------------- host orchestration ----------------
static void run_prep(const float* w, unsigned* wb, unsigned* ws, int CO, int CIN)
{
    int nz = (CO + 63) / 64;
    int total = nz * (CIN >> 4) * 4608;
    prep_w_kernel<<<(total + 255) / 256, 256>>>(w, wb, ws, CO, CIN, nz);
}

static void run_conv(const float* in, const unsigned* wb, const unsigned* ws,
                     const float* bias, const float* scale,
                     float* out, int N, int CIN, int CO, int H, int W)
{
    dim3 grid((W + 31) / 32, ((H + 3) / 4) * N, (CO + 63) / 64);
    conv3x3_mma_kernel<<<grid, 256, CONV_SMEM_BYTES>>>(in, wb, ws, bias, scale,
                                                       out, N, CIN, CO, H, W);
}

static int g_gn_slot;

static void run_gn(const float* x, float* out, const float* g, const float* b,
                   float* stats_base, int N, int C, int H, int W, int groups, int relu)
{
    int Cg = C / groups;
    int E = Cg * H * W;
    int ng = N * groups;
    float* stats = stats_base + (g_gn_slot++) * 128;
    int slabs = E / 8192; if (slabs < 1) slabs = 1; if (slabs > 64) slabs = 64;
    dim3 gs(slabs, ng);
    gn_stats_kernel<<<gs, 256>>>(x, stats, E);
    int total4 = (N * C * H * W) >> 2;
    gn_apply_kernel<<<(total4 + 255) / 256, 256>>>(x, stats, g, b, out,
                                                   total4, (C * H * W) >> 2, (H * W) >> 2,
                                                   Cg, groups, relu, 1.0f / (float)E);
}

extern "C" void kernel_launch(void* const* d_in, const int* in_sizes, int n_in,
                              void* d_out, int out_size)
{
    const int HS[5] = {96, 48, 24, 12, 6};
    const int WS[5] = {160, 80, 40, 20, 10};

    const float* f[5];
    for (int i = 0; i < 5; i++) f[i] = (const float*)d_in[i];
    const float* head_w     = (const float*)d_in[5];
    const float* head_gn_g  = (const float*)d_in[6];
    const float* head_gn_b  = (const float*)d_in[7];
    const float* head_out_w = (const float*)d_in[8];
    const float* head_out_b = (const float*)d_in[9];
    const float* scales     = (const float*)d_in[10];
    const float* ref_w      = (const float*)d_in[11];
    const float* ref_gn_g   = (const float*)d_in[12];
    const float* ref_gn_b   = (const float*)d_in[13];
    const float* tow_w      = (const float*)d_in[14];
    const float* tow_gn_g   = (const float*)d_in[15];
    const float* tow_gn_b   = (const float*)d_in[16];
    const float* out_w      = (const float*)d_in[17];
    const float* out_gn_g   = (const float*)d_in[18];
    const float* out_gn_b   = (const float*)d_in[19];

    float *bufA, *bufB, *mA, *mB, *mC, *stats, *params, *dyn;
    unsigned *wb, *ws;
    cudaGetSymbolAddress((void**)&bufA,   g_bufA);
    cudaGetSymbolAddress((void**)&bufB,   g_bufB);
    cudaGetSymbolAddress((void**)&mA,     g_mA);
    cudaGetSymbolAddress((void**)&mB,     g_mB);
    cudaGetSymbolAddress((void**)&mC,     g_mC);
    cudaGetSymbolAddress((void**)&stats,  g_stats);
    cudaGetSymbolAddress((void**)&params, g_params);
    cudaGetSymbolAddress((void**)&dyn,    g_dyn);
    cudaGetSymbolAddress((void**)&wb,     g_wb);
    cudaGetSymbolAddress((void**)&ws,     g_ws);

    cudaFuncSetAttribute(conv3x3_mma_kernel,
                         cudaFuncAttributeMaxDynamicSharedMemorySize, CONV_SMEM_BYTES);

    float* out = (float*)d_out;
    g_gn_slot = 0;

    zero_kernel<<<(32*128 + 255) / 256, 256>>>(stats, 32*128);

    // output offsets
    size_t pred_off[5];
    size_t off = 0;
    for (int L = 0; L < 5; L++) {
        pred_off[L] = off;
        off += (size_t)2 * 254 * HS[L] * WS[L];
    }
    size_t mf_off = off;
    off += (size_t)2 * 8 * 96 * 160;
    size_t ml_off = off;

    // per-level arena offsets (256-channel features)
    size_t lo[5];
    size_t a = 0;
    for (int L = 0; L < 5; L++) { lo[L] = a; a += (size_t)2 * 256 * HS[L] * WS[L]; }

    // ---- head branches: layer-outer so each weight prep is reused across 5 levels ----
    for (int i = 0; i < 4; i++) {
        run_prep(head_w + (size_t)i * 256 * 256 * 9, wb, ws, 256, 256);
        for (int L = 0; L < 5; L++) {
            const float* src = (i == 0) ? f[L] : (bufB + lo[L]);
            run_conv(src, wb, ws, nullptr, nullptr, bufA + lo[L], 2, 256, 256, HS[L], WS[L]);
            run_gn(bufA + lo[L], bufB + lo[L], head_gn_g + i * 256, head_gn_b + i * 256,
                   stats, 2, 256, HS[L], WS[L], 32, 1);
        }
    }
    run_prep(head_out_w, wb, ws, 254, 256);
    for (int L = 0; L < 5; L++) {
        run_conv(bufB + lo[L], wb, ws, head_out_b, scales + L,
                 out + pred_off[L], 2, 256, 254, HS[L], WS[L]);
    }

    // ---- mask branch: refine levels 0..2, accumulate at level-0 resolution ----
    for (int i = 0; i < 3; i++) {
        int H = HS[i], W = WS[i];
        run_prep(ref_w + (size_t)i * 128 * 256 * 9, wb, ws, 128, 256);
        run_conv(f[i], wb, ws, nullptr, nullptr, mA, 2, 256, 128, H, W);
        if (i == 0) {
            run_gn(mA, mC, ref_gn_g + i * 128, ref_gn_b + i * 128, stats, 2, 128, H, W, 1, 1);
        } else {
            run_gn(mA, mB, ref_gn_g + i * 128, ref_gn_b + i * 128, stats, 2, 128, H, W, 1, 1);
            int tot = 2 * 128 * 96 * 160;
            resize_kernel<<<(tot + 255) / 256, 256>>>(mB, mC, 2 * 128, H, W, 96, 160, 1);
        }
    }
    // ---- tower ----
    const float* tx = mC;
    for (int i = 0; i < 4; i++) {
        run_prep(tow_w + (size_t)i * 128 * 128 * 9, wb, ws, 128, 128);
        run_conv(tx, wb, ws, nullptr, nullptr, mA, 2, 128, 128, 96, 160);
        float* dst = (i % 2 == 0) ? mB : mC;
        run_gn(mA, dst, tow_gn_g + i * 128, tow_gn_b + i * 128, stats, 2, 128, 96, 160, 1, 1);
        tx = dst;
    }
    // ---- out 1x1 conv -> GN -> relu -> mask_feats ----
    {
        int HW = 96 * 160;
        conv1x1_8_kernel<<<(2 * HW + 255) / 256, 256>>>(tx, out_w, mA, 2, 128, HW);
        run_gn(mA, out + mf_off, out_gn_g, out_gn_b, stats, 2, 8, 96, 160, 1, 1);
    }
    // ---- dynamic conv head ----
    gather_params_kernel<<<(200 * 169 + 255) / 256, 256>>>(out + pred_off[0], params);
    {
        dim3 g(200, 60);
        dyn_mlp_kernel<<<g, 256>>>(out + mf_off, params, dyn);
    }
    {
        int tot = 200 * 192 * 320;
        resize_kernel<<<(tot + 255) / 256, 256>>>(dyn, out + ml_off, 200, 96, 160, 192, 320, 0);
    }
}